// round 7
// baseline (speedup 1.0000x reference)
#include <cuda_runtime.h>
#include <cuda_bf16.h>
#include <math.h>
#include <stdint.h>

// ---------------------------------------------------------------------------
// MMD^2 (RBF, gamma=1), 8192x16 fp32, via mma.sync.m16n8k16 bf16 (sm_100 base).
//
// Coords scaled by sqrt(2*log2e), split x = hi + mid (bf16).
// A row: [hi(16) mid(16) hi(16) mid(16) | nh nm nl 1 1 1 | 0...]   (80 used)
// B row: [hi(16) hi(16) mid(16) mid(16) | 1 1 1 nh nm nl | 0...]
// => GEMM output D = dot_s(a,b) - 0.5|a|_s^2 - 0.5|b|_s^2 = -log2e*||a-b||^2.
// Per-pair value = ex2(D); only the tile SUM is needed, so the mma
// fragment->element mapping is irrelevant. Upper-triangle tiles only.
// Mainloop and ex2-epilogue are FUSED per 16-column group so the tensor
// pipe and MUFU pipe overlap within each warp.
// ---------------------------------------------------------------------------

#define NSRC   8192
#define D      16
#define NP     16384
#define TILE   128
#define TB     (NP / TILE)                 // 128
#define NBLK   (TB * (TB + 1) / 2)         // 8256
#define SQ2L   1.6986436004918308f         // sqrt(2*log2(e))
#define KPAD   88                          // padded row length (bf16)
#define ROWB   (KPAD * 2)                  // 176 bytes per row
#define NKC    5                           // K chunks of 16 (cols 0..79)
#define ATILEB (TILE * ROWB)               // 22528 bytes per tile side

// per point: u0,u1 = hi(16 bf16), u2,u3 = mid, u4 = normA unit, u5 = normB unit
__device__ uint4  g_S[NP * 6];
__device__ double g_part[NBLK];

// ---------------- helpers ----------------
__device__ __forceinline__ float ex2(float x) {
    float r; asm("ex2.approx.f32 %0, %1;" : "=f"(r) : "f"(x)); return r;
}
__device__ __forceinline__ uint32_t smem_u32(const void* p) {
    uint32_t a;
    asm("{ .reg .u64 t; cvta.to.shared.u64 t, %1; cvt.u32.u64 %0, t; }"
        : "=r"(a) : "l"(p));
    return a;
}
__device__ __forceinline__ void ldsm4(uint32_t* r, uint32_t addr) {
    asm volatile("ldmatrix.sync.aligned.m8n8.x4.shared.b16 {%0,%1,%2,%3}, [%4];"
                 : "=r"(r[0]), "=r"(r[1]), "=r"(r[2]), "=r"(r[3]) : "r"(addr));
}
__device__ __forceinline__ void mma16816(float* c, const uint32_t* a,
                                         uint32_t b0, uint32_t b1) {
    asm volatile("mma.sync.aligned.m16n8k16.row.col.f32.bf16.bf16.f32 "
                 "{%0,%1,%2,%3}, {%4,%5,%6,%7}, {%8,%9}, {%0,%1,%2,%3};"
                 : "+f"(c[0]), "+f"(c[1]), "+f"(c[2]), "+f"(c[3])
                 : "r"(a[0]), "r"(a[1]), "r"(a[2]), "r"(a[3]), "r"(b0), "r"(b1));
}
__device__ __forceinline__ int tri_row_start(int t) {
    return t * TB - ((t * (t - 1)) >> 1);
}

// ---------------------------------------------------------------------------
// Kernel 1: scale, hi/mid split, 3-way-split norm units.
// ---------------------------------------------------------------------------
__global__ void __launch_bounds__(256) split_kernel(const float* __restrict__ src,
                                                    const float* __restrict__ tgt) {
    int p = blockIdx.x * 256 + threadIdx.x;
    if (p >= NP) return;
    const float* x = (p < NSRC) ? (src + (size_t)p * D) : (tgt + (size_t)(p - NSRC) * D);

    uint4 u[6];
    __nv_bfloat16* hi  = (__nv_bfloat16*)&u[0];
    __nv_bfloat16* mid = (__nv_bfloat16*)&u[2];
    __nv_bfloat16* nA  = (__nv_bfloat16*)&u[4];
    __nv_bfloat16* nB  = (__nv_bfloat16*)&u[5];

    float ns = 0.f;
#pragma unroll
    for (int d = 0; d < D; d++) {
        float v = x[d] * SQ2L;
        ns = fmaf(v, v, ns);
        __nv_bfloat16 h = __float2bfloat16(v);
        float r1 = v - __bfloat162float(h);
        hi[d]  = h;
        mid[d] = __float2bfloat16(r1);
    }
    float na = -0.5f * ns;
    __nv_bfloat16 nh = __float2bfloat16(na);
    float nr1 = na - __bfloat162float(nh);
    __nv_bfloat16 nm = __float2bfloat16(nr1);
    __nv_bfloat16 nl = __float2bfloat16(nr1 - __bfloat162float(nm));
    const __nv_bfloat16 one  = __float2bfloat16(1.0f);
    const __nv_bfloat16 zero = __float2bfloat16(0.0f);

    nA[0] = nh;  nA[1] = nm;  nA[2] = nl;  nA[3] = one; nA[4] = one; nA[5] = one;
    nA[6] = zero; nA[7] = zero;
    nB[0] = one; nB[1] = one; nB[2] = one; nB[3] = nh;  nB[4] = nm;  nB[5] = nl;
    nB[6] = zero; nB[7] = zero;

    uint4* out = g_S + (size_t)p * 6;
#pragma unroll
    for (int i = 0; i < 6; i++) out[i] = u[i];
}

// ---------------------------------------------------------------------------
// Kernel 2: pairwise 128x128 tiles via bf16 mma.sync, fused MUFU epilogue.
// Warp w: rows (w&3)*32 + {0,16}, cols (w>>2)*64 in four 16-col groups.
// ---------------------------------------------------------------------------
__global__ void __launch_bounds__(256, 3) pair_kernel() {
    extern __shared__ __align__(16) char dsm[];
    __shared__ float wsum[8];

    const int bid  = blockIdx.x;
    const int tid  = threadIdx.x;
    const int lane = tid & 31;
    const int w    = tid >> 5;

    int ti = (int)((2.0 * TB + 1.0 - sqrt((2.0 * TB + 1.0) * (2.0 * TB + 1.0)
                                          - 8.0 * (double)bid)) * 0.5);
    while (tri_row_start(ti + 1) <= bid) ti++;
    while (tri_row_start(ti) > bid) ti--;
    const int tj = ti + (bid - tri_row_start(ti));

    // ---- build A/B tiles in SMEM (row stride 176B; conflict-free ldmatrix) ----
    {
        const int  row = tid & 127;
        const bool isA = tid < 128;
        const uint4* srow = g_S + (size_t)(((isA ? ti : tj) * TILE) + row) * 6;
        char* rbase = dsm + (isA ? 0 : ATILEB) + row * ROWB;

        uint4 u[6];
#pragma unroll
        for (int i = 0; i < 6; i++) u[i] = srow[i];

        // 16B column chunks (11 = 176B):
        // A: [hi hi mid mid hi hi mid mid nA 0 0]
        // B: [hi hi hi hi mid mid mid mid nB 0 0]
        const int mapA[11] = {0,1, 2,3, 0,1, 2,3, 4, -1, -1};
        const int mapB[11] = {0,1, 0,1, 2,3, 2,3, 5, -1, -1};
#pragma unroll
        for (int c = 0; c < 11; c++) {
            int s = isA ? mapA[c] : mapB[c];
            uint4 v = (s >= 0) ? u[s] : make_uint4(0u, 0u, 0u, 0u);
            *(uint4*)(rbase + c * 16) = v;
        }
    }
    __syncthreads();

    const uint32_t sA = smem_u32(dsm);
    const uint32_t sB = sA + ATILEB;
    const int mbase = (w & 3) * 32;
    const int nbase = (w >> 2) * 64;

    // ---- preload all A fragments (5 kc x 2 m-tiles) ----
    const uint32_t aRow   = (uint32_t)(mbase + (lane & 7) + ((lane >> 3) & 1) * 8);
    const uint32_t aAddr0 = sA + aRow * ROWB + ((lane >> 4) & 1) * 16;
    const uint32_t aAddr1 = aAddr0 + 16 * ROWB;
    uint32_t a0[NKC][4], a1[NKC][4];
#pragma unroll
    for (int kc = 0; kc < NKC; kc++) {
        ldsm4(a0[kc], aAddr0 + kc * 32);
        ldsm4(a1[kc], aAddr1 + kc * 32);
    }

    const uint32_t bRowQ = (uint32_t)((lane & 7) + ((lane >> 4) & 1) * 8);
    const uint32_t bColH = ((lane >> 3) & 1) * 16;

    // ---- fused mainloop + epilogue per 16-column group ----
    float s0 = 0.f, s1 = 0.f, s2 = 0.f, s3 = 0.f;
#pragma unroll
    for (int q = 0; q < 4; q++) {
        const uint32_t bAddr = sB + (uint32_t)(nbase + 16 * q + bRowQ) * ROWB + bColH;
        float acc[2][2][4];
#pragma unroll
        for (int mt = 0; mt < 2; mt++)
#pragma unroll
            for (int h = 0; h < 2; h++)
#pragma unroll
                for (int e = 0; e < 4; e++) acc[mt][h][e] = 0.f;

#pragma unroll
        for (int kc = 0; kc < NKC; kc++) {
            uint32_t b[4];
            ldsm4(b, bAddr + kc * 32);
            mma16816(acc[0][0], a0[kc], b[0], b[1]);
            mma16816(acc[0][1], a0[kc], b[2], b[3]);
            mma16816(acc[1][0], a1[kc], b[0], b[1]);
            mma16816(acc[1][1], a1[kc], b[2], b[3]);
        }
        // immediate MUFU epilogue for this group (overlaps next group's MMAs)
#pragma unroll
        for (int mt = 0; mt < 2; mt++)
#pragma unroll
            for (int h = 0; h < 2; h++) {
                s0 += ex2(acc[mt][h][0]);
                s1 += ex2(acc[mt][h][1]);
                s2 += ex2(acc[mt][h][2]);
                s3 += ex2(acc[mt][h][3]);
            }
    }

    float tsum = (s0 + s1) + (s2 + s3);
#pragma unroll
    for (int off = 16; off; off >>= 1)
        tsum += __shfl_xor_sync(0xffffffffu, tsum, off);
    if (lane == 0) wsum[w] = tsum;
    __syncthreads();

    if (tid == 0) {
        double t = 0.0;
#pragma unroll
        for (int x = 0; x < 8; x++) t += (double)wsum[x];
        double wgt = (ti == tj) ? 1.0 : 2.0;
        double sgn = ((ti < TB / 2) == (tj < TB / 2)) ? 1.0 : -1.0;
        g_part[bid] = t * wgt * sgn;
    }
}

// ---------------------------------------------------------------------------
// Kernel 3: fixed-order double reduction -> scalar
// ---------------------------------------------------------------------------
__global__ void __launch_bounds__(512) finish_kernel(float* out) {
    __shared__ double s[512];
    const int tid = threadIdx.x;
    const double2* p2 = (const double2*)g_part;       // NBLK even
    double t0 = 0.0, t1 = 0.0;
#pragma unroll 4
    for (int i = tid; i < NBLK / 2; i += 512) {
        double2 v = p2[i];
        t0 += v.x;
        t1 += v.y;
    }
    s[tid] = t0 + t1;
    __syncthreads();
#pragma unroll
    for (int off = 256; off; off >>= 1) {
        if (tid < off) s[tid] += s[tid + off];
        __syncthreads();
    }
    if (tid == 0) out[0] = (float)(s[0] / 67108864.0);   // / n^2, n = 8192
}

// ---------------------------------------------------------------------------
extern "C" void kernel_launch(void* const* d_in, const int* in_sizes, int n_in,
                              void* d_out, int out_size) {
    const float* src = (const float*)d_in[0];
    const float* tgt = (const float*)d_in[1];

    const int smem_bytes = 2 * ATILEB;     // 45056 B
    cudaFuncSetAttribute(pair_kernel, cudaFuncAttributeMaxDynamicSharedMemorySize,
                         smem_bytes);

    split_kernel<<<(NP + 255) / 256, 256>>>(src, tgt);
    pair_kernel<<<NBLK, 256, smem_bytes>>>();
    finish_kernel<<<1, 512>>>((float*)d_out);
}